// round 15
// baseline (speedup 1.0000x reference)
#include <cuda_runtime.h>
#include <mma.h>
#include <cuda_bf16.h>
#include <cstdint>
#include <cstddef>

using namespace nvcuda;

#define BB 4
#define PP 256
#define FIN 512
#define FOUT 512
#define NROWS (BB*PP)   // 1024

// ---------------- device scratch (no allocations allowed) -------------------
__device__ __nv_bfloat16 g_Hb[NROWS * FOUT]; // fc output, bf16-rounded (1 MB)
__device__ float g_ss2[8][NROWS];            // per-nblock partial sum-of-squares
__device__ float g_Spart[128][16 * 256];     // K-split Gram partials (2 MB)
__device__ unsigned long long g_h1[NROWS];
__device__ unsigned long long g_h2[NROWS];
__device__ double g_loss = 0.0;              // reset by final combiner
__device__ unsigned int g_batch[BB];         // per-batch producer arrivals
__device__ unsigned int g_bdone[BB];         // per-batch consumer completions
__device__ unsigned int g_pair[64];          // per-pair arrival (self-reset)
__device__ unsigned int g_done = 0;          // combiner count (self-reset)

// ---------------- cp.async helpers ------------------------------------------
__device__ __forceinline__ void cp16(uint32_t saddr, const void* gptr) {
    asm volatile("cp.async.cg.shared.global [%0], [%1], 16;" :: "r"(saddr), "l"(gptr));
}
#define CP_COMMIT() asm volatile("cp.async.commit_group;" ::: "memory")
#define CP_WAIT(n)  asm volatile("cp.async.wait_group %0;" :: "n"(n) : "memory")

__device__ __forceinline__ unsigned long long mix64(unsigned long long x) {
    x ^= x >> 30; x *= 0xbf58476d1ce4e5b9ULL;
    x ^= x >> 27; x *= 0x94d049bb133111ebULL;
    x ^= x >> 31;
    return x;
}

// ================= single fused kernel =======================================
// 128 CTAs x 512 thr. Phase 1 (all CTAs): hash + bf16 GEMM1 tile -> g_Hb/g_ss2,
// then arrive on g_batch[cta>>5]. Phase 2 (all CTAs, re-mapped): wait for own
// batch's 32 producers, split-K Gram partial, pair-combine, softmax+KL.
__global__ __launch_bounds__(512, 1)
void mega(const float* __restrict__ A, const float* __restrict__ labels,
          const float* __restrict__ W, const float* __restrict__ bias,
          float* __restrict__ out) {
    extern __shared__ __align__(16) char dynraw[];
    const int cta = blockIdx.x;
    const int tid = threadIdx.x;
    const int wid = tid >> 5, lane = tid & 31;

    // ======== phase 0: hash (warps 0..7 -> 1024 label rows) ==================
    if (wid < 8) {
        int gwarp = cta * 8 + wid;
        const float4* row = reinterpret_cast<const float4*>(labels + (size_t)gwarp * FIN);
        unsigned long long h1 = 0ull, h2 = 0ull;
#pragma unroll
        for (int i = 0; i < 4; i++) {
            float4 v = row[lane + 32 * i];
            int fb = (lane + 32 * i) * 4;
            float vv[4] = {v.x, v.y, v.z, v.w};
#pragma unroll
            for (int j = 0; j < 4; j++) {
                unsigned int bits = __float_as_uint(vv[j]);
                if (vv[j] == 0.0f) bits = 0u;
                unsigned long long x = (unsigned long long)bits
                    ^ ((unsigned long long)(fb + j + 1) * 0x9E3779B97F4A7C15ULL);
                h1 += mix64(x);
                h2 += mix64(x ^ 0xA5A5A5A5DEADBEEFULL);
            }
        }
#pragma unroll
        for (int o = 16; o > 0; o >>= 1) {
            h1 += __shfl_down_sync(0xffffffffu, h1, o);
            h2 += __shfl_down_sync(0xffffffffu, h2, o);
        }
        if (lane == 0) { g_h1[gwarp] = h1; g_h2[gwarp] = h2; }
    }

    // ======== phase 1: bf16 GEMM1 64x64 tile (R14 k1 body) ===================
    {
        __nv_bfloat16* dynb = reinterpret_cast<__nv_bfloat16*>(dynraw);
        const int nb = cta & 7;
        const int n0 = nb * 64;
        const int m0 = (cta >> 3) * 64;
        __nv_bfloat16* Asm = dynb;                // [2][64][72]
        __nv_bfloat16* Bsm = dynb + 2 * 64 * 72;  // [2][64][72]
        const int wr = wid >> 2, wc = wid & 3;

        float4 pa[2], pb[2];
        auto LDG = [&](int s) {
#pragma unroll
            for (int q = 0; q < 2; q++) {
                int idx = tid + q * 512;
                int row = idx >> 4, f = idx & 15;
                pa[q] = *reinterpret_cast<const float4*>(A + (size_t)(m0 + row) * FIN + s * 64 + f * 4);
                pb[q] = *reinterpret_cast<const float4*>(W + (size_t)(n0 + row) * FIN + s * 64 + f * 4);
            }
        };
        auto STS = [&](int buf) {
#pragma unroll
            for (int q = 0; q < 2; q++) {
                int idx = tid + q * 512;
                int row = idx >> 4, f = idx & 15;
                __nv_bfloat162 a0 = __float22bfloat162_rn(make_float2(pa[q].x, pa[q].y));
                __nv_bfloat162 a1 = __float22bfloat162_rn(make_float2(pa[q].z, pa[q].w));
                __nv_bfloat162 b0 = __float22bfloat162_rn(make_float2(pb[q].x, pb[q].y));
                __nv_bfloat162 b1 = __float22bfloat162_rn(make_float2(pb[q].z, pb[q].w));
                uint2 va, vb;
                va.x = reinterpret_cast<uint32_t&>(a0); va.y = reinterpret_cast<uint32_t&>(a1);
                vb.x = reinterpret_cast<uint32_t&>(b0); vb.y = reinterpret_cast<uint32_t&>(b1);
                *reinterpret_cast<uint2*>(Asm + (size_t)buf * 4608 + row * 72 + f * 4) = va;
                *reinterpret_cast<uint2*>(Bsm + (size_t)buf * 4608 + row * 72 + f * 4) = vb;
            }
        };

        wmma::fragment<wmma::accumulator, 16, 16, 16, float> c0;
        wmma::fill_fragment(c0, 0.0f);

        LDG(0);
        STS(0);
        __syncthreads();

#pragma unroll 1
        for (int s = 0; s < 8; s++) {
            const int buf = s & 1;
            if (s + 1 < 8) LDG(s + 1);
#pragma unroll
            for (int ks = 0; ks < 4; ks++) {
                wmma::fragment<wmma::matrix_a, 16, 16, 16, __nv_bfloat16, wmma::row_major> a;
                wmma::fragment<wmma::matrix_b, 16, 16, 16, __nv_bfloat16, wmma::col_major> b0;
                wmma::load_matrix_sync(a,  Asm + (size_t)buf * 4608 + (wr * 16) * 72 + ks * 16, 72);
                wmma::load_matrix_sync(b0, Bsm + (size_t)buf * 4608 + (wc * 16) * 72 + ks * 16, 72);
                wmma::mma_sync(c0, a, b0, c0);
            }
            if (s + 1 < 8) STS(buf ^ 1);
            __syncthreads();
        }

        float* stage = reinterpret_cast<float*>(dynb);   // [64][68]
        wmma::store_matrix_sync(stage + (size_t)(wr * 16) * 68 + wc * 16, c0, 68, wmma::mem_row_major);
        __syncthreads();
#pragma unroll
        for (int t = 0; t < 2; t++) {
            int f4 = tid + t * 512;
            int row = f4 >> 4, c4 = (f4 & 15) * 4;
            float4 v = *reinterpret_cast<const float4*>(stage + (size_t)row * 68 + c4);
            float4 bv = *reinterpret_cast<const float4*>(bias + n0 + c4);
            __nv_bfloat162 lo = __float22bfloat162_rn(make_float2(v.x + bv.x, v.y + bv.y));
            __nv_bfloat162 hi = __float22bfloat162_rn(make_float2(v.z + bv.z, v.w + bv.w));
            *reinterpret_cast<__nv_bfloat162*>(g_Hb + (size_t)(m0 + row) * FOUT + n0 + c4)     = lo;
            *reinterpret_cast<__nv_bfloat162*>(g_Hb + (size_t)(m0 + row) * FOUT + n0 + c4 + 2) = hi;
            float lx = __bfloat162float(lo.x), ly = __bfloat162float(lo.y);
            float hx = __bfloat162float(hi.x), hy = __bfloat162float(hi.y);
            *reinterpret_cast<float4*>(stage + (size_t)row * 68 + c4) = make_float4(lx, ly, hx, hy);
        }
        __syncthreads();
        {
            int row = tid >> 3;
            int cg = (tid & 7) * 8;
            float ss = 0.0f;
#pragma unroll
            for (int i = 0; i < 2; i++) {
                float4 v = *reinterpret_cast<const float4*>(stage + (size_t)row * 68 + cg + i * 4);
                ss += v.x * v.x + v.y * v.y + v.z * v.z + v.w * v.w;
            }
            ss += __shfl_xor_sync(0xffffffffu, ss, 1);
            ss += __shfl_xor_sync(0xffffffffu, ss, 2);
            ss += __shfl_xor_sync(0xffffffffu, ss, 4);
            if ((tid & 7) == 0) g_ss2[nb][m0 + row] = ss;
        }
    }

    // ======== release: producer arrival on this CTA's batch ==================
    __threadfence();
    __syncthreads();
    if (tid == 0) atomicAdd(&g_batch[cta >> 5], 1u);

    // ======== phase 2: split-K Gram + pair-combine + softmax + KL ============
    {
        const int b    = cta >> 5;                // same batch as produced
        const int tile = (cta >> 1) & 15;
        const int kh   = cta & 1;
        const int m0 = tile * 16;

        // wait for all 32 producers of batch b
        if (tid == 0) {
            while (atomicAdd(&g_batch[b], 0u) < 32u) { __nanosleep(32); }
        }
        __syncthreads();
        __threadfence();

        float* dynf = reinterpret_cast<float*>(dynraw);
        __nv_bfloat16* Asm = reinterpret_cast<__nv_bfloat16*>(dynf);            // [16][264]
        __nv_bfloat16* Bsm = reinterpret_cast<__nv_bfloat16*>(dynf) + 16 * 264; // [4][256][72]
        __shared__ float inv_s[PP];
        __shared__ unsigned long long sh1[PP];
        __shared__ unsigned long long sh2[PP];
        __shared__ double wsum[16];
        __shared__ unsigned int sflag;

        const char* Hb8 = reinterpret_cast<const char*>(g_Hb + (size_t)b * PP * FOUT);
        const uint32_t Asm_s = (uint32_t)__cvta_generic_to_shared(Asm);
        const uint32_t Bsm_s = (uint32_t)__cvta_generic_to_shared(Bsm);

        // prologue: issue all 4 groups (A+B0, B1, B2, B3)
        {
            int row = tid >> 5, f = tid & 31;
            cp16(Asm_s + (uint32_t)row * 528u + (uint32_t)f * 16u,
                 Hb8 + (size_t)(m0 + row) * 1024 + kh * 512 + f * 16);
#pragma unroll
            for (int s = 0; s < 4; s++) {
#pragma unroll
                for (int q = 0; q < 4; q++) {
                    int idx = tid + q * 512;
                    int r = idx >> 3, ff = idx & 7;
                    cp16(Bsm_s + (uint32_t)s * 36864u + (uint32_t)r * 144u + (uint32_t)ff * 16u,
                         Hb8 + (size_t)r * 1024 + kh * 512 + s * 128 + ff * 16);
                }
                CP_COMMIT();
            }
        }

        if (tid < 256) {
            int q = tid;
            float ss = 0.0f;
#pragma unroll
            for (int nb = 0; nb < 8; nb++) ss += g_ss2[nb][b * PP + q];
            inv_s[q] = 1.0f / fmaxf(sqrtf(ss), 1e-12f);
            sh1[q] = g_h1[b * PP + q];
            sh2[q] = g_h2[b * PP + q];
        }

        wmma::fragment<wmma::accumulator, 16, 16, 16, float> c0;
        wmma::fill_fragment(c0, 0.0f);

#pragma unroll 1
        for (int s = 0; s < 4; s++) {
            if      (s == 0) { CP_WAIT(3); }
            else if (s == 1) { CP_WAIT(2); }
            else if (s == 2) { CP_WAIT(1); }
            else             { CP_WAIT(0); }
            __syncthreads();
#pragma unroll
            for (int ks = 0; ks < 4; ks++) {
                wmma::fragment<wmma::matrix_a, 16, 16, 16, __nv_bfloat16, wmma::row_major> a;
                wmma::fragment<wmma::matrix_b, 16, 16, 16, __nv_bfloat16, wmma::col_major> b0;
                wmma::load_matrix_sync(a, Asm + s * 64 + ks * 16, 264);
                wmma::load_matrix_sync(b0, Bsm + (size_t)s * 256 * 72 + (size_t)(wid * 16) * 72 + ks * 16, 72);
                wmma::mma_sync(c0, a, b0, c0);
            }
        }
        __syncthreads();

        float* stageS = dynf;                     // [16][260]
        wmma::store_matrix_sync(stageS + wid * 16, c0, 260, wmma::mem_row_major);
        __syncthreads();

        // write partial, arrive on pair counter
#pragma unroll
        for (int q = 0; q < 2; q++) {
            int idx = tid + q * 512;
            int row = idx >> 6, c4 = (idx & 63) * 4;
            float4 v = *reinterpret_cast<const float4*>(stageS + (size_t)row * 260 + c4);
            *reinterpret_cast<float4*>(&g_Spart[cta][row * 256 + c4]) = v;
        }
        __threadfence();
        __syncthreads();
        if (tid == 0) sflag = atomicAdd(&g_pair[cta >> 1], 1u);
        __syncthreads();

        bool combiner = (sflag != 0);
        if (combiner) {
            if (tid == 0) g_pair[cta >> 1] = 0;
            __threadfence();
            const float* peer = g_Spart[cta ^ 1];
#pragma unroll
            for (int q = 0; q < 2; q++) {
                int idx = tid + q * 512;
                int row = idx >> 6, c4 = (idx & 63) * 4;
                float4 p = *reinterpret_cast<const float4*>(peer + row * 256 + c4);
                float* d = stageS + (size_t)row * 260 + c4;
                d[0] += p.x; d[1] += p.y; d[2] += p.z; d[3] += p.w;
            }
            __syncthreads();

            const float INV_TAU = 1.0f / 0.07f;
            {
                const int pl = wid;
                const float* Sr = stageS + (size_t)pl * 260;
                const float ip = inv_s[m0 + pl] * INV_TAU;
                float s[8];
                float mx = -1e30f;
#pragma unroll
                for (int j = 0; j < 8; j++) {
                    int q = lane + 32 * j;
                    s[j] = Sr[q] * ip * inv_s[q];
                    mx = fmaxf(mx, s[j]);
                }
#pragma unroll
                for (int o = 16; o > 0; o >>= 1) mx = fmaxf(mx, __shfl_xor_sync(0xffffffffu, mx, o));
                float z = 0.0f;
#pragma unroll
                for (int j = 0; j < 8; j++) z += __expf(s[j] - mx);
#pragma unroll
                for (int o = 16; o > 0; o >>= 1) z += __shfl_xor_sync(0xffffffffu, z, o);
                float lse = mx + logf(z);

                unsigned long long h1p = sh1[m0 + pl], h2p = sh2[m0 + pl];
                int cnt = 0;
                bool match[8];
#pragma unroll
                for (int j = 0; j < 8; j++) {
                    int q = lane + 32 * j;
                    match[j] = (sh1[q] == h1p) && (sh2[q] == h2p);
                    cnt += match[j] ? 1 : 0;
                }
#pragma unroll
                for (int o = 16; o > 0; o >>= 1) cnt += __shfl_xor_sync(0xffffffffu, cnt, o);

                float logn = logf((float)cnt);
                float contrib = 0.0f;
#pragma unroll
                for (int j = 0; j < 8; j++) {
                    if (match[j]) {
                        float lp = s[j] - lse;
                        lp = fminf(fmaxf(lp, -11.512925464970229f),      // log(1e-5)
                                   -1.0000050000290891e-05f);            // log(1-1e-5)
                        contrib += (-logn - lp);
                    }
                }
#pragma unroll
                for (int o = 16; o > 0; o >>= 1) contrib += __shfl_xor_sync(0xffffffffu, contrib, o);
                if (lane == 0) wsum[wid] = (double)contrib / (double)cnt;
            }
            __syncthreads();
            if (tid == 0) {
                double blk = 0.0;
#pragma unroll
                for (int i = 0; i < 16; i++) blk += wsum[i];
                atomicAdd(&g_loss, blk);
                __threadfence();
                if (atomicAdd(&g_done, 1u) == 63u) {     // last combiner
                    double l = atomicAdd(&g_loss, 0.0);
                    out[0] = (float)(l * (1.0 / (double)(BB * PP)));
                    g_loss = 0.0;                        // reset for next replay
                    g_done = 0;
                    __threadfence();
                }
            }
        }

        // consumer completion -> reset batch counters for next replay
        if (tid == 0) {
            unsigned int d = atomicAdd(&g_bdone[b], 1u);
            if (d == 31u) {
                g_batch[b] = 0;
                g_bdone[b] = 0;
                __threadfence();
            }
        }
    }
}

// ================= launch ====================================================
extern "C" void kernel_launch(void* const* d_in, const int* in_sizes, int n_in,
                              void* d_out, int out_size) {
    const float* inputs = (const float*)d_in[0];
    const float* labels = (const float*)d_in[1];
    const float* W      = (const float*)d_in[2];
    const float* bias   = (const float*)d_in[3];
    float* out = (float*)d_out;

    const int SMEM = 16 * 264 * 2 + 4 * 256 * 72 * 2;        // 155904 B (phase-2 max)
    cudaFuncSetAttribute(mega, cudaFuncAttributeMaxDynamicSharedMemorySize, SMEM);
    mega<<<128, 512, SMEM>>>(inputs, labels, W, bias, out);
}

// round 16
// speedup vs baseline: 1.0830x; 1.0830x over previous
#include <cuda_runtime.h>
#include <mma.h>
#include <cuda_bf16.h>
#include <cstdint>
#include <cstddef>

using namespace nvcuda;

#define BB 4
#define PP 256
#define FIN 512
#define FOUT 512
#define NROWS (BB*PP)   // 1024

// ---------------- device scratch (no allocations allowed) -------------------
__device__ __nv_bfloat16 g_Hb[NROWS * FOUT]; // fc output, bf16-rounded (1 MB)
__device__ float g_ss2[8][NROWS];            // per-nblock partial sum-of-squares
__device__ float g_Spart[128][16 * 256];     // K-split Gram partials (2 MB)
__device__ unsigned long long g_h1[NROWS];
__device__ unsigned long long g_h2[NROWS];
__device__ double g_loss;
__device__ unsigned int g_pair[64];          // per-pair arrival (self-reset)
__device__ unsigned int g_done = 0;          // combiner count (self-reset)

// ---------------- cp.async helpers ------------------------------------------
__device__ __forceinline__ void cp16(uint32_t saddr, const void* gptr) {
    asm volatile("cp.async.cg.shared.global [%0], [%1], 16;" :: "r"(saddr), "l"(gptr));
}
#define CP_COMMIT() asm volatile("cp.async.commit_group;" ::: "memory")
#define CP_WAIT(n)  asm volatile("cp.async.wait_group %0;" :: "n"(n) : "memory")

__device__ __forceinline__ unsigned long long mix64(unsigned long long x) {
    x ^= x >> 30; x *= 0xbf58476d1ce4e5b9ULL;
    x ^= x >> 27; x *= 0x94d049bb133111ebULL;
    x ^= x >> 31;
    return x;
}

// ================= K1: hash + bf16 GEMM1 + bf16 round + norm partials ========
// 128 CTAs x 512 thr (16 warps, 4x4, warp tile 16x16), 64x64 tiles,
// BK=128 (4 chunks), reg-staged dbl-buffer, stride-136 bf16 smem.
__global__ __launch_bounds__(512, 1)
void k1_gemm(const float* __restrict__ A, const float* __restrict__ labels,
             const float* __restrict__ W, const float* __restrict__ bias) {
    extern __shared__ __align__(16) __nv_bfloat16 dynb[];   // As[2][64][136], Bs[2][64][136]
    const int cta = blockIdx.x;
    const int tid = threadIdx.x;
    const int wid = tid >> 5, lane = tid & 31;

    if (cta == 0 && tid == 0) g_loss = 0.0;

    // ---- hash: warps 0..7 -> 1024 label rows
    if (wid < 8) {
        int gwarp = cta * 8 + wid;
        const float4* row = reinterpret_cast<const float4*>(labels + (size_t)gwarp * FIN);
        unsigned long long h1 = 0ull, h2 = 0ull;
#pragma unroll
        for (int i = 0; i < 4; i++) {
            float4 v = row[lane + 32 * i];
            int fb = (lane + 32 * i) * 4;
            float vv[4] = {v.x, v.y, v.z, v.w};
#pragma unroll
            for (int j = 0; j < 4; j++) {
                unsigned int bits = __float_as_uint(vv[j]);
                if (vv[j] == 0.0f) bits = 0u;
                unsigned long long x = (unsigned long long)bits
                    ^ ((unsigned long long)(fb + j + 1) * 0x9E3779B97F4A7C15ULL);
                h1 += mix64(x);
                h2 += mix64(x ^ 0xA5A5A5A5DEADBEEFULL);
            }
        }
#pragma unroll
        for (int o = 16; o > 0; o >>= 1) {
            h1 += __shfl_down_sync(0xffffffffu, h1, o);
            h2 += __shfl_down_sync(0xffffffffu, h2, o);
        }
        if (lane == 0) { g_h1[gwarp] = h1; g_h2[gwarp] = h2; }
    }

    // ---- GEMM: 64x64 tile, BK=128, 4 chunks
    const int nb = cta & 7;
    const int n0 = nb * 64;
    const int m0 = (cta >> 3) * 64;
    __nv_bfloat16* Asm = dynb;                 // [2][64][136]
    __nv_bfloat16* Bsm = dynb + 2 * 64 * 136;  // [2][64][136]
    const int wr = wid >> 2, wc = wid & 3;

    float4 pa[4], pb[4];
    auto LDG = [&](int s) {
#pragma unroll
        for (int q = 0; q < 4; q++) {
            int idx = tid + q * 512;           // 0..2047
            int row = idx >> 5, f = idx & 31;  // 64 rows x 32 f4
            pa[q] = *reinterpret_cast<const float4*>(A + (size_t)(m0 + row) * FIN + s * 128 + f * 4);
            pb[q] = *reinterpret_cast<const float4*>(W + (size_t)(n0 + row) * FIN + s * 128 + f * 4);
        }
    };
    auto STS = [&](int buf) {
#pragma unroll
        for (int q = 0; q < 4; q++) {
            int idx = tid + q * 512;
            int row = idx >> 5, f = idx & 31;
            __nv_bfloat162 a0 = __float22bfloat162_rn(make_float2(pa[q].x, pa[q].y));
            __nv_bfloat162 a1 = __float22bfloat162_rn(make_float2(pa[q].z, pa[q].w));
            __nv_bfloat162 b0 = __float22bfloat162_rn(make_float2(pb[q].x, pb[q].y));
            __nv_bfloat162 b1 = __float22bfloat162_rn(make_float2(pb[q].z, pb[q].w));
            uint2 va, vb;
            va.x = reinterpret_cast<uint32_t&>(a0); va.y = reinterpret_cast<uint32_t&>(a1);
            vb.x = reinterpret_cast<uint32_t&>(b0); vb.y = reinterpret_cast<uint32_t&>(b1);
            *reinterpret_cast<uint2*>(Asm + (size_t)buf * 8704 + row * 136 + f * 4) = va;
            *reinterpret_cast<uint2*>(Bsm + (size_t)buf * 8704 + row * 136 + f * 4) = vb;
        }
    };

    wmma::fragment<wmma::accumulator, 16, 16, 16, float> c0;
    wmma::fill_fragment(c0, 0.0f);

    LDG(0);
    STS(0);
    __syncthreads();

#pragma unroll 1
    for (int s = 0; s < 4; s++) {
        const int buf = s & 1;
        if (s + 1 < 4) LDG(s + 1);
#pragma unroll
        for (int ks = 0; ks < 8; ks++) {
            wmma::fragment<wmma::matrix_a, 16, 16, 16, __nv_bfloat16, wmma::row_major> a;
            wmma::fragment<wmma::matrix_b, 16, 16, 16, __nv_bfloat16, wmma::col_major> b0;
            wmma::load_matrix_sync(a,  Asm + (size_t)buf * 8704 + (wr * 16) * 136 + ks * 16, 136);
            wmma::load_matrix_sync(b0, Bsm + (size_t)buf * 8704 + (wc * 16) * 136 + ks * 16, 136);
            wmma::mma_sync(c0, a, b0, c0);
        }
        if (s + 1 < 4) STS(buf ^ 1);
        __syncthreads();
    }

    // ---- epilogue: stage fp32, +bias, round bf16, store g_Hb, SS partials
    float* stage = reinterpret_cast<float*>(dynb);   // [64][68]
    wmma::store_matrix_sync(stage + (size_t)(wr * 16) * 68 + wc * 16, c0, 68, wmma::mem_row_major);
    __syncthreads();
#pragma unroll
    for (int t = 0; t < 2; t++) {
        int f4 = tid + t * 512;
        int row = f4 >> 4, c4 = (f4 & 15) * 4;
        float4 v = *reinterpret_cast<const float4*>(stage + (size_t)row * 68 + c4);
        float4 bv = *reinterpret_cast<const float4*>(bias + n0 + c4);
        __nv_bfloat162 lo = __float22bfloat162_rn(make_float2(v.x + bv.x, v.y + bv.y));
        __nv_bfloat162 hi = __float22bfloat162_rn(make_float2(v.z + bv.z, v.w + bv.w));
        *reinterpret_cast<__nv_bfloat162*>(g_Hb + (size_t)(m0 + row) * FOUT + n0 + c4)     = lo;
        *reinterpret_cast<__nv_bfloat162*>(g_Hb + (size_t)(m0 + row) * FOUT + n0 + c4 + 2) = hi;
        float lx = __bfloat162float(lo.x), ly = __bfloat162float(lo.y);
        float hx = __bfloat162float(hi.x), hy = __bfloat162float(hi.y);
        *reinterpret_cast<float4*>(stage + (size_t)row * 68 + c4) = make_float4(lx, ly, hx, hy);
    }
    __syncthreads();
    {
        int row = tid >> 3;
        int cg = (tid & 7) * 8;
        float ss = 0.0f;
#pragma unroll
        for (int i = 0; i < 2; i++) {
            float4 v = *reinterpret_cast<const float4*>(stage + (size_t)row * 68 + cg + i * 4);
            ss += v.x * v.x + v.y * v.y + v.z * v.z + v.w * v.w;
        }
        ss += __shfl_xor_sync(0xffffffffu, ss, 1);
        ss += __shfl_xor_sync(0xffffffffu, ss, 2);
        ss += __shfl_xor_sync(0xffffffffu, ss, 4);
        if ((tid & 7) == 0) g_ss2[nb][m0 + row] = ss;
    }
}

// ================= K2: split-K Gram + pair-combine + softmax + KL ============
// 128 CTAs x 512 thr. CTA = (b, 16-row tile, khalf): partial Gram over 256 K
// cols as 2 chunks of 128, both cp.async groups issued up front (2 buffers).
// Second arriver of each pair combines partials and does softmax+KL.
__global__ __launch_bounds__(512, 1)
void k2_gram_kl(float* __restrict__ out) {
    extern __shared__ __align__(16) float dynf[];
    __nv_bfloat16* Asm = reinterpret_cast<__nv_bfloat16*>(dynf);            // [16][264]
    __nv_bfloat16* Bsm = reinterpret_cast<__nv_bfloat16*>(dynf) + 16 * 264; // [2][256][136]
    __shared__ float inv_s[PP];
    __shared__ unsigned long long sh1[PP];
    __shared__ unsigned long long sh2[PP];
    __shared__ double wsum[16];
    __shared__ unsigned int sflag;

    const int cta  = blockIdx.x;
    const int b    = cta >> 5;                // 0..3
    const int tile = (cta >> 1) & 15;         // 0..15
    const int kh   = cta & 1;                 // K half
    const int m0 = tile * 16;
    const int tid = threadIdx.x;
    const int wid = tid >> 5, lane = tid & 31;
    const char* Hb8 = reinterpret_cast<const char*>(g_Hb + (size_t)b * PP * FOUT);

    const uint32_t Asm_s = (uint32_t)__cvta_generic_to_shared(Asm);
    const uint32_t Bsm_s = (uint32_t)__cvta_generic_to_shared(Bsm);

    // ---- prologue: group0 = A + B-chunk0; group1 = B-chunk1
    {
        // A: 16 rows x 256 bf16 (this K half) = 512 x 16B, 1 per thread
        int row = tid >> 5, f = tid & 31;
        cp16(Asm_s + (uint32_t)row * 528u + (uint32_t)f * 16u,
             Hb8 + (size_t)(m0 + row) * 1024 + kh * 512 + f * 16);
#pragma unroll
        for (int s = 0; s < 2; s++) {
#pragma unroll
            for (int q = 0; q < 8; q++) {     // B chunk: 256 rows x 16 x 16B
                int idx = tid + q * 512;      // 0..4095
                int r = idx >> 4, ff = idx & 15;
                cp16(Bsm_s + (uint32_t)s * 69632u + (uint32_t)r * 272u + (uint32_t)ff * 16u,
                     Hb8 + (size_t)r * 1024 + kh * 512 + s * 256 + ff * 16);
            }
            CP_COMMIT();
        }
    }

    // metadata (plain loads, overlap with async copies)
    if (tid < 256) {
        int q = tid;
        float ss = 0.0f;
#pragma unroll
        for (int nb = 0; nb < 8; nb++) ss += g_ss2[nb][b * PP + q];
        inv_s[q] = 1.0f / fmaxf(sqrtf(ss), 1e-12f);
        sh1[q] = g_h1[b * PP + q];
        sh2[q] = g_h2[b * PP + q];
    }

    wmma::fragment<wmma::accumulator, 16, 16, 16, float> c0;
    wmma::fill_fragment(c0, 0.0f);

#pragma unroll 1
    for (int s = 0; s < 2; s++) {
        if (s == 0) { CP_WAIT(1); } else { CP_WAIT(0); }
        __syncthreads();
#pragma unroll
        for (int ks = 0; ks < 8; ks++) {
            wmma::fragment<wmma::matrix_a, 16, 16, 16, __nv_bfloat16, wmma::row_major> a;
            wmma::fragment<wmma::matrix_b, 16, 16, 16, __nv_bfloat16, wmma::col_major> b0;
            wmma::load_matrix_sync(a, Asm + s * 128 + ks * 16, 264);
            wmma::load_matrix_sync(b0, Bsm + (size_t)s * 256 * 136 + (size_t)(wid * 16) * 136 + ks * 16, 136);
            wmma::mma_sync(c0, a, b0, c0);
        }
    }
    __syncthreads();                          // all smem mma reads done

    // ---- stage partial S tile [16][260] (overlays Asm/Bsm)
    float* stageS = dynf;
    wmma::store_matrix_sync(stageS + wid * 16, c0, 260, wmma::mem_row_major);
    __syncthreads();

    // ---- write partial to gmem, arrive on pair counter
#pragma unroll
    for (int q = 0; q < 2; q++) {
        int idx = tid + q * 512;              // 1024 f4
        int row = idx >> 6, c4 = (idx & 63) * 4;
        float4 v = *reinterpret_cast<const float4*>(stageS + (size_t)row * 260 + c4);
        *reinterpret_cast<float4*>(&g_Spart[cta][row * 256 + c4]) = v;
    }
    __threadfence();
    __syncthreads();
    if (tid == 0) sflag = atomicAdd(&g_pair[cta >> 1], 1u);
    __syncthreads();
    if (sflag == 0) return;                   // first arriver: done

    // ---- second arriver: combine with peer partial, then softmax + KL
    if (tid == 0) g_pair[cta >> 1] = 0;       // reset for next graph replay
    __threadfence();
    const float* peer = g_Spart[cta ^ 1];
#pragma unroll
    for (int q = 0; q < 2; q++) {
        int idx = tid + q * 512;
        int row = idx >> 6, c4 = (idx & 63) * 4;
        float4 p = *reinterpret_cast<const float4*>(peer + row * 256 + c4);
        float* d = stageS + (size_t)row * 260 + c4;
        d[0] += p.x; d[1] += p.y; d[2] += p.z; d[3] += p.w;
    }
    __syncthreads();

    const float INV_TAU = 1.0f / 0.07f;
    {
        const int pl = wid;                   // 16 warps x 1 row
        const float* Sr = stageS + (size_t)pl * 260;
        const float ip = inv_s[m0 + pl] * INV_TAU;
        float s[8];
        float mx = -1e30f;
#pragma unroll
        for (int j = 0; j < 8; j++) {
            int q = lane + 32 * j;
            s[j] = Sr[q] * ip * inv_s[q];
            mx = fmaxf(mx, s[j]);
        }
#pragma unroll
        for (int o = 16; o > 0; o >>= 1) mx = fmaxf(mx, __shfl_xor_sync(0xffffffffu, mx, o));
        float z = 0.0f;
#pragma unroll
        for (int j = 0; j < 8; j++) z += __expf(s[j] - mx);
#pragma unroll
        for (int o = 16; o > 0; o >>= 1) z += __shfl_xor_sync(0xffffffffu, z, o);
        float lse = mx + logf(z);

        unsigned long long h1p = sh1[m0 + pl], h2p = sh2[m0 + pl];
        int cnt = 0;
        bool match[8];
#pragma unroll
        for (int j = 0; j < 8; j++) {
            int q = lane + 32 * j;
            match[j] = (sh1[q] == h1p) && (sh2[q] == h2p);
            cnt += match[j] ? 1 : 0;
        }
#pragma unroll
        for (int o = 16; o > 0; o >>= 1) cnt += __shfl_xor_sync(0xffffffffu, cnt, o);

        float logn = logf((float)cnt);
        float contrib = 0.0f;
#pragma unroll
        for (int j = 0; j < 8; j++) {
            if (match[j]) {
                float lp = s[j] - lse;
                lp = fminf(fmaxf(lp, -11.512925464970229f),      // log(1e-5)
                           -1.0000050000290891e-05f);            // log(1-1e-5)
                contrib += (-logn - lp);
            }
        }
#pragma unroll
        for (int o = 16; o > 0; o >>= 1) contrib += __shfl_xor_sync(0xffffffffu, contrib, o);
        if (lane == 0) wsum[wid] = (double)contrib / (double)cnt;
    }
    __syncthreads();
    if (tid == 0) {
        double blk = 0.0;
#pragma unroll
        for (int i = 0; i < 16; i++) blk += wsum[i];
        atomicAdd(&g_loss, blk);
        __threadfence();
        if (atomicAdd(&g_done, 1u) == 63u) {     // last combiner writes output
            *(volatile unsigned int*)&g_done = 0;
            double l = atomicAdd(&g_loss, 0.0);
            out[0] = (float)(l * (1.0 / (double)(BB * PP)));
        }
    }
}

// ================= launch ====================================================
extern "C" void kernel_launch(void* const* d_in, const int* in_sizes, int n_in,
                              void* d_out, int out_size) {
    const float* inputs = (const float*)d_in[0];
    const float* labels = (const float*)d_in[1];
    const float* W      = (const float*)d_in[2];
    const float* bias   = (const float*)d_in[3];
    float* out = (float*)d_out;

    const int K1_SMEM = 2 * 2 * 64 * 136 * 2;                // 69632 B
    const int K2_SMEM = 16 * 264 * 2 + 2 * 256 * 136 * 2;    // 147712 B
    cudaFuncSetAttribute(k1_gemm,    cudaFuncAttributeMaxDynamicSharedMemorySize, K1_SMEM);
    cudaFuncSetAttribute(k2_gram_kl, cudaFuncAttributeMaxDynamicSharedMemorySize, K2_SMEM);

    k1_gemm<<<128, 512, K1_SMEM>>>(inputs, labels, W, bias);
    k2_gram_kl<<<128, 512, K2_SMEM>>>(out);
}